// round 9
// baseline (speedup 1.0000x reference)
#include <cuda_runtime.h>
#include <cuda_bf16.h>
#include <cstdint>

// Problem constants
#define Bn 32
#define Ln 256
#define Dn 256
#define Hn 256
#define En 8
#define NLn 4
#define Kc 4
#define MROWS (Bn*En*Ln)     // 65536

#define SSTRIDE 264          // gemm smem stride
#define RSTRIDE 264          // rec hbuf stride (bf16 elems)

__device__ __forceinline__ float fast_tanh(float x)
{
    float y;
    asm("tanh.approx.f32 %0, %1;" : "=f"(y) : "f"(x));
    return y;
}

__device__ __forceinline__ uint32_t s2u(const void* p)
{
    uint32_t a;
    asm("{ .reg .u64 t; cvta.to.shared.u64 t, %1; cvt.u32.u64 %0, t; }"
        : "=r"(a) : "l"(p));
    return a;
}

// pack two fp32 -> bf16x2 (first arg in low half)
__device__ __forceinline__ unsigned int pbf2(float lo, float hi)
{
    unsigned int r;
    asm("cvt.rn.bf16x2.f32 %0, %1, %2;" : "=r"(r) : "f"(hi), "f"(lo));
    return r;
}

__device__ __forceinline__ float bhi(float x)
{
    return __bfloat162float(__float2bfloat16(x));
}

#define MMA_BF16(c, a, b) \
    asm volatile( \
        "mma.sync.aligned.m16n8k16.row.col.f32.bf16.bf16.f32 " \
        "{%0,%1,%2,%3}, {%4,%5,%6,%7}, {%8,%9}, {%0,%1,%2,%3};" \
        : "+f"((c)[0]), "+f"((c)[1]), "+f"((c)[2]), "+f"((c)[3]) \
        : "r"((a)[0]), "r"((a)[1]), "r"((a)[2]), "r"((a)[3]), \
          "r"((b)[0]), "r"((b)[1]))

__device__ __forceinline__ void mbar_wait_cluster(uint32_t mbar, uint32_t parity)
{
    asm volatile(
        "{\n\t"
        ".reg .pred P1;\n\t"
        "WL_%=:\n\t"
        "mbarrier.try_wait.parity.acquire.cluster.shared::cta.b64 P1, [%0], %1;\n\t"
        "@P1 bra.uni WD_%=;\n\t"
        "bra.uni WL_%=;\n\t"
        "WD_%=:\n\t"
        "}" :: "r"(mbar), "r"(parity) : "memory");
}

// Scratch (device globals - no allocation allowed)
__device__ float g_ln[Bn*Ln*Dn];                 // 8 MB
__device__ float g_u[Bn*Ln*Dn];                  // 8 MB
__device__ float g_y[(size_t)Bn*En*Ln*Hn];       // 64 MB
__device__ float g_pre[(size_t)Bn*En*Ln*Hn];     // 64 MB

// ---------------------------------------------------------------------------
// LayerNorm
// ---------------------------------------------------------------------------
__global__ void ln_kernel(const float* __restrict__ x, const float* __restrict__ g,
                          const float* __restrict__ bb, float* __restrict__ out)
{
    int token = blockIdx.x;
    int t = threadIdx.x;
    __shared__ float red[8];
    __shared__ float meanv, rstdv;

    float v = x[(size_t)token * Dn + t];

    float s = v;
    #pragma unroll
    for (int o = 16; o > 0; o >>= 1) s += __shfl_xor_sync(0xffffffffu, s, o);
    if ((t & 31) == 0) red[t >> 5] = s;
    __syncthreads();
    if (t == 0) {
        float m = 0.f;
        #pragma unroll
        for (int i = 0; i < 8; i++) m += red[i];
        meanv = m * (1.0f / Dn);
    }
    __syncthreads();

    float d = v - meanv;
    float sq = d * d;
    #pragma unroll
    for (int o = 16; o > 0; o >>= 1) sq += __shfl_xor_sync(0xffffffffu, sq, o);
    if ((t & 31) == 0) red[t >> 5] = sq;
    __syncthreads();
    if (t == 0) {
        float vv = 0.f;
        #pragma unroll
        for (int i = 0; i < 8; i++) vv += red[i];
        rstdv = rsqrtf(vv * (1.0f / Dn) + 1e-5f);
    }
    __syncthreads();

    out[(size_t)token * Dn + t] = d * rstdv * g[t] + bb[t];
}

// ---------------------------------------------------------------------------
// Depthwise causal conv1d (K=4, left pad 3) + bias
// ---------------------------------------------------------------------------
__global__ void conv_kernel(const float* __restrict__ ln, const float* __restrict__ cw,
                            const float* __restrict__ cb, float* __restrict__ u)
{
    int idx = blockIdx.x * 256 + threadIdx.x;
    int d  = idx & 255;
    int l  = (idx >> 8) & 255;
    int b0 = idx >> 16;
    float acc = cb[d];
    #pragma unroll
    for (int j = 0; j < Kc; j++) {
        int ls = l - (Kc - 1) + j;
        if (ls >= 0)
            acc += ln[((size_t)b0 * Ln + ls) * Dn + d] * cw[d * Kc + j];
    }
    u[idx] = acc;
}

// ---------------------------------------------------------------------------
// mma.sync bf16 split GEMM (round-5, proven): pre = (x*r) @ Wih^T * s + b
// ---------------------------------------------------------------------------
#define OFF_AHI 0
#define OFF_ALO (128*SSTRIDE)
#define OFF_BHI (256*SSTRIDE)
#define OFF_BLO (320*SSTRIDE)
#define SM3_ELEMS (384*SSTRIDE)
#define SM3_BYTES (SM3_ELEMS*2)

__global__ __launch_bounds__(256, 1)
void gemm3_kernel(const float* __restrict__ inx, const float* __restrict__ Wih,
                  const float* __restrict__ rv, const float* __restrict__ sv,
                  const float* __restrict__ bv, float* __restrict__ pre, int layer0)
{
    extern __shared__ __align__(16) __nv_bfloat16 sm[];
    int tid = threadIdx.x;
    int wid = tid >> 5;
    int lane = tid & 31;
    int bm = blockIdx.x;

    int eT = (bm >> 1) & 7;
    const float* rrow = rv + (size_t)eT * 256;

    {
        int row = tid >> 1;
        int kh  = (tid & 1) * 128;
        int rowA = bm * 128 + row;
        size_t srcRow = layer0 ? ((size_t)(rowA >> 11) * 256 + (rowA & 255))
                               : (size_t)rowA;
        const float* arow = inx + srcRow * 256 + kh;
        const float* rr   = rrow + kh;
        __nv_bfloat16* ahi = sm + OFF_AHI + row * SSTRIDE + kh;
        __nv_bfloat16* alo = sm + OFF_ALO + row * SSTRIDE + kh;
        #pragma unroll
        for (int g = 0; g < 32; g++) {
            float4 av = *(const float4*)(arow + g * 4);
            float4 rv4 = *(const float4*)(rr + g * 4);
            av.x *= rv4.x; av.y *= rv4.y; av.z *= rv4.z; av.w *= rv4.w;
            float vv[4] = {av.x, av.y, av.z, av.w};
            float hi[4], lo[4];
            #pragma unroll
            for (int qq = 0; qq < 4; qq++) {
                hi[qq] = bhi(vv[qq]);
                lo[qq] = vv[qq] - hi[qq];
            }
            *(uint2*)(ahi + g * 4) = make_uint2(pbf2(hi[0], hi[1]), pbf2(hi[2], hi[3]));
            *(uint2*)(alo + g * 4) = make_uint2(pbf2(lo[0], lo[1]), pbf2(lo[2], lo[3]));
        }
    }

    int warp_m = wid & 3;
    int warp_n = wid >> 2;
    int grp = lane >> 2;
    int tg  = lane & 3;

    for (int bn = 0; bn < 4; bn++) {
        __syncthreads();
        {
            int row = tid >> 2;
            int kq  = (tid & 3) * 64;
            const float* brow = Wih + (size_t)(bn * 64 + row) * 256 + kq;
            __nv_bfloat16* bhi_p = sm + OFF_BHI + row * SSTRIDE + kq;
            __nv_bfloat16* blo_p = sm + OFF_BLO + row * SSTRIDE + kq;
            #pragma unroll
            for (int g = 0; g < 16; g++) {
                float4 bvv = *(const float4*)(brow + g * 4);
                float vv[4] = {bvv.x, bvv.y, bvv.z, bvv.w};
                float hi[4], lo[4];
                #pragma unroll
                for (int qq = 0; qq < 4; qq++) {
                    hi[qq] = bhi(vv[qq]);
                    lo[qq] = vv[qq] - hi[qq];
                }
                *(uint2*)(bhi_p + g * 4) = make_uint2(pbf2(hi[0], hi[1]), pbf2(hi[2], hi[3]));
                *(uint2*)(blo_p + g * 4) = make_uint2(pbf2(lo[0], lo[1]), pbf2(lo[2], lo[3]));
            }
        }
        __syncthreads();

        float acc[2][4][4];
        #pragma unroll
        for (int mt = 0; mt < 2; mt++)
            #pragma unroll
            for (int n8 = 0; n8 < 4; n8++)
                #pragma unroll
                for (int qq = 0; qq < 4; qq++) acc[mt][n8][qq] = 0.f;

        #pragma unroll 4
        for (int k0 = 0; k0 < 256; k0 += 16) {
            uint32_t ahi_f[2][4], alo_f[2][4];
            #pragma unroll
            for (int mt = 0; mt < 2; mt++) {
                int r0 = warp_m * 32 + mt * 16 + grp;
                const __nv_bfloat16* pHi = sm + OFF_AHI + r0 * SSTRIDE + k0 + tg * 2;
                const __nv_bfloat16* pLo = sm + OFF_ALO + r0 * SSTRIDE + k0 + tg * 2;
                ahi_f[mt][0] = *(const uint32_t*)(pHi);
                ahi_f[mt][1] = *(const uint32_t*)(pHi + 8 * SSTRIDE);
                ahi_f[mt][2] = *(const uint32_t*)(pHi + 8);
                ahi_f[mt][3] = *(const uint32_t*)(pHi + 8 * SSTRIDE + 8);
                alo_f[mt][0] = *(const uint32_t*)(pLo);
                alo_f[mt][1] = *(const uint32_t*)(pLo + 8 * SSTRIDE);
                alo_f[mt][2] = *(const uint32_t*)(pLo + 8);
                alo_f[mt][3] = *(const uint32_t*)(pLo + 8 * SSTRIDE + 8);
            }
            uint32_t bhi_f[4][2], blo_f[4][2];
            #pragma unroll
            for (int n8 = 0; n8 < 4; n8++) {
                int c0 = warp_n * 32 + n8 * 8 + grp;
                const __nv_bfloat16* pHi = sm + OFF_BHI + c0 * SSTRIDE + k0 + tg * 2;
                const __nv_bfloat16* pLo = sm + OFF_BLO + c0 * SSTRIDE + k0 + tg * 2;
                bhi_f[n8][0] = *(const uint32_t*)(pHi);
                bhi_f[n8][1] = *(const uint32_t*)(pHi + 8);
                blo_f[n8][0] = *(const uint32_t*)(pLo);
                blo_f[n8][1] = *(const uint32_t*)(pLo + 8);
            }
            #pragma unroll
            for (int mt = 0; mt < 2; mt++)
                #pragma unroll
                for (int n8 = 0; n8 < 4; n8++) {
                    MMA_BF16(acc[mt][n8], ahi_f[mt], bhi_f[n8]);
                    MMA_BF16(acc[mt][n8], ahi_f[mt], blo_f[n8]);
                    MMA_BF16(acc[mt][n8], alo_f[mt], bhi_f[n8]);
                }
        }

        const float* srow = sv + (size_t)eT * 256;
        #pragma unroll
        for (int mt = 0; mt < 2; mt++) {
            int rloc = warp_m * 32 + mt * 16 + grp;
            size_t row0 = (size_t)bm * 128 + rloc;
            #pragma unroll
            for (int n8 = 0; n8 < 4; n8++) {
                int col = bn * 64 + warp_n * 32 + n8 * 8 + tg * 2;
                float s0 = srow[col], s1 = srow[col + 1];
                float b0 = bv[col], b1 = bv[col + 1];
                float2 o0, o1;
                o0.x = acc[mt][n8][0] * s0 + b0;
                o0.y = acc[mt][n8][1] * s1 + b1;
                o1.x = acc[mt][n8][2] * s0 + b0;
                o1.y = acc[mt][n8][3] * s1 + b1;
                *(float2*)(pre + row0 * 256 + col) = o0;
                *(float2*)(pre + (row0 + 8) * 256 + col) = o1;
            }
        }
    }
}

// ---------------------------------------------------------------------------
// rec3: tensor-core recurrence with the ROUND-3-PROVEN symmetric cluster sync.
// 16 clusters x 2 CTAs, 16 chains per cluster. CTA rank q owns outs
// [q*128, q*128+128). 8 warps = (kh: K-half 0/1) x (nw: N32 slice).
// mbar count = 256: ALL threads arrive on the peer's mbar each step (t<255),
// ALL threads wait on their own mbar at step top (t>0). W-hi fragments in
// regs, W-lo in smem; h as bf16 hi/lo in double-buffered smem; peer half of
// h delivered via st.shared::cluster before the release-arrive.
// ---------------------------------------------------------------------------
#define R2_HI   0
#define R2_LO   16896
#define R2_RED  33792
#define R2_WLO  42496
#define R2_MBAR 108032
#define R2_TOTAL 108048
#define PAR_STRIDE 4224      // bf16 elems per hbuf parity (16*264)

__global__ __launch_bounds__(256, 1) __cluster_dims__(2, 1, 1)
void rec3_kernel(const float* __restrict__ pre, const float* __restrict__ Whh,
                 float* __restrict__ yout, float* __restrict__ hlast)
{
    extern __shared__ __align__(16) char sm2[];
    __nv_bfloat16* hb_hi = (__nv_bfloat16*)(sm2 + R2_HI);
    __nv_bfloat16* hb_lo = (__nv_bfloat16*)(sm2 + R2_LO);
    float* red = (float*)(sm2 + R2_RED);             // [128][17]
    uint32_t* wlo = (uint32_t*)(sm2 + R2_WLO);       // [8 warps][2048]

    int q = blockIdx.x;           // cluster rank
    int cc = blockIdx.y;          // cluster id 0..15
    int tid = threadIdx.x;
    int wid = tid >> 5;
    int lane = tid & 31;
    int grp = lane >> 2;
    int tg = lane & 3;
    int kh = wid >> 2;            // K half 0/1
    int nw = wid & 3;             // N32 slice

    // ---- W fragments: hi in regs, lo in smem (one-time) ---------------------
    uint32_t wh[8][4][2];
    uint32_t* wl_base = wlo + (size_t)wid * 2048;
    {
        int row0 = q * 128 + nw * 32;
        #pragma unroll
        for (int c8 = 0; c8 < 8; c8++) {
            #pragma unroll
            for (int tn = 0; tn < 4; tn++) {
                const float* wr = Whh + (size_t)(row0 + tn * 8 + grp) * Hn
                                + kh * 128 + c8 * 16 + tg * 2;
                float2 u0 = *(const float2*)wr;
                float2 u1 = *(const float2*)(wr + 8);
                float h00 = bhi(u0.x), h01 = bhi(u0.y);
                float h10 = bhi(u1.x), h11 = bhi(u1.y);
                wh[c8][tn][0] = pbf2(h00, h01);
                wh[c8][tn][1] = pbf2(h10, h11);
                wl_base[((c8 * 4 + tn) * 2 + 0) * 32 + lane] = pbf2(u0.x - h00, u0.y - h01);
                wl_base[((c8 * 4 + tn) * 2 + 1) * 32 + lane] = pbf2(u1.x - h10, u1.y - h11);
            }
        }
    }

    // zero hbuf (both parities, hi+lo = first 33792 bytes)
    {
        uint32_t* z = (uint32_t*)sm2;
        for (int i = tid; i < 33792 / 4; i += 256) z[i] = 0u;
    }
    uint32_t my_mbar = s2u(sm2 + R2_MBAR);
    if (tid == 0)
        asm volatile("mbarrier.init.shared.b64 [%0], 256;" :: "r"(my_mbar) : "memory");
    __syncthreads();
    asm volatile("barrier.cluster.arrive.aligned;\n\t"
                 "barrier.cluster.wait.aligned;" ::: "memory");

    uint32_t peer_mbar, peer_hi_u, peer_lo_u;
    asm("mapa.shared::cluster.u32 %0, %1, %2;" : "=r"(peer_mbar) : "r"(my_mbar), "r"(q ^ 1));
    uint32_t hi_u = s2u(hb_hi), lo_u = s2u(hb_lo);
    asm("mapa.shared::cluster.u32 %0, %1, %2;" : "=r"(peer_hi_u) : "r"(hi_u), "r"(q ^ 1));
    asm("mapa.shared::cluster.u32 %0, %1, %2;" : "=r"(peer_lo_u) : "r"(lo_u), "r"(q ^ 1));

    int gc0 = q * 128 + nw * 32 + tg * 2;            // first out col (epilogue)
    size_t ch0 = (size_t)cc * 16 + grp;              // chain (row grp)
    const float* pp0 = pre + ch0 * Ln * Hn + gc0;
    const float* pp1 = pp0 + (size_t)8 * Ln * Hn;
    float* yy0 = yout + ch0 * Ln * Hn + gc0;
    float* yy1 = yy0 + (size_t)8 * Ln * Hn;
    float* myred = red + (nw * 32 + lane) * 17;

    uint32_t pq = 0, ph = 0;

    for (int t = 0; t < Ln; t++) {
        // prefetch pre before the wait (latency hidden by the spin)
        float2 pv0[4], pv1[4];
        if (kh == 0) {
            #pragma unroll
            for (int tn = 0; tn < 4; tn++) {
                pv0[tn] = *(const float2*)(pp0 + (size_t)t * Hn + tn * 8);
                pv1[tn] = *(const float2*)(pp1 + (size_t)t * Hn + tn * 8);
            }
        }
        // symmetric wait (round-3-proven): ALL threads wait each step
        if (t > 0) { mbar_wait_cluster(my_mbar, ph); ph ^= 1u; }

        float acc[4][4];
        #pragma unroll
        for (int tn = 0; tn < 4; tn++)
            #pragma unroll
            for (int j = 0; j < 4; j++) acc[tn][j] = 0.f;

        const __nv_bfloat16* Hhi = hb_hi + pq * PAR_STRIDE;
        const __nv_bfloat16* Hlo = hb_lo + pq * PAR_STRIDE;
        #pragma unroll
        for (int c8 = 0; c8 < 8; c8++) {
            int k0 = kh * 128 + c8 * 16 + tg * 2;
            uint32_t ah[4], al[4];
            ah[0] = *(const uint32_t*)(Hhi + grp * RSTRIDE + k0);
            ah[1] = *(const uint32_t*)(Hhi + (grp + 8) * RSTRIDE + k0);
            ah[2] = *(const uint32_t*)(Hhi + grp * RSTRIDE + k0 + 8);
            ah[3] = *(const uint32_t*)(Hhi + (grp + 8) * RSTRIDE + k0 + 8);
            al[0] = *(const uint32_t*)(Hlo + grp * RSTRIDE + k0);
            al[1] = *(const uint32_t*)(Hlo + (grp + 8) * RSTRIDE + k0);
            al[2] = *(const uint32_t*)(Hlo + grp * RSTRIDE + k0 + 8);
            al[3] = *(const uint32_t*)(Hlo + (grp + 8) * RSTRIDE + k0 + 8);
            #pragma unroll
            for (int tn = 0; tn < 4; tn++) {
                uint32_t wl2[2];
                wl2[0] = wl_base[((c8 * 4 + tn) * 2 + 0) * 32 + lane];
                wl2[1] = wl_base[((c8 * 4 + tn) * 2 + 1) * 32 + lane];
                MMA_BF16(acc[tn], ah, wh[c8][tn]);
                MMA_BF16(acc[tn], ah, wl2);
                MMA_BF16(acc[tn], al, wh[c8][tn]);
            }
        }

        if (kh == 1) {
            #pragma unroll
            for (int tn = 0; tn < 4; tn++)
                #pragma unroll
                for (int j = 0; j < 4; j++)
                    myred[tn * 4 + j] = acc[tn][j];
        }
        __syncthreads();

        if (kh == 0) {
            #pragma unroll
            for (int tn = 0; tn < 4; tn++)
                #pragma unroll
                for (int j = 0; j < 4; j++)
                    acc[tn][j] += myred[tn * 4 + j];

            int np = (int)(pq ^ 1u);
            #pragma unroll
            for (int tn = 0; tn < 4; tn++) {
                float v00 = acc[tn][0] + pv0[tn].x;
                float v01 = acc[tn][1] + pv0[tn].y;
                float v10 = acc[tn][2] + pv1[tn].x;
                float v11 = acc[tn][3] + pv1[tn].y;
                float h00 = fast_tanh(v00), h01 = fast_tanh(v01);
                float h10 = fast_tanh(v10), h11 = fast_tanh(v11);

                *(float2*)(yy0 + (size_t)t * Hn + tn * 8) = make_float2(h00, h01);
                *(float2*)(yy1 + (size_t)t * Hn + tn * 8) = make_float2(h10, h11);

                float b00 = bhi(h00), b01 = bhi(h01);
                float b10 = bhi(h10), b11 = bhi(h11);
                uint32_t hp0 = pbf2(b00, b01);
                uint32_t hp1 = pbf2(b10, b11);
                uint32_t lp0 = pbf2(h00 - b00, h01 - b01);
                uint32_t lp1 = pbf2(h10 - b10, h11 - b11);

                int gc = gc0 + tn * 8;
                int off0 = np * PAR_STRIDE + grp * RSTRIDE + gc;
                int off1 = np * PAR_STRIDE + (grp + 8) * RSTRIDE + gc;
                *(uint32_t*)(hb_hi + off0) = hp0;
                *(uint32_t*)(hb_hi + off1) = hp1;
                *(uint32_t*)(hb_lo + off0) = lp0;
                *(uint32_t*)(hb_lo + off1) = lp1;

                if (t < Ln - 1) {
                    asm volatile("st.shared::cluster.b32 [%0], %1;"
                                 :: "r"(peer_hi_u + off0 * 2), "r"(hp0));
                    asm volatile("st.shared::cluster.b32 [%0], %1;"
                                 :: "r"(peer_hi_u + off1 * 2), "r"(hp1));
                    asm volatile("st.shared::cluster.b32 [%0], %1;"
                                 :: "r"(peer_lo_u + off0 * 2), "r"(lp0));
                    asm volatile("st.shared::cluster.b32 [%0], %1;"
                                 :: "r"(peer_lo_u + off1 * 2), "r"(lp1));
                } else if (hlast != nullptr) {
                    *(float2*)(hlast + ch0 * Hn + gc) = make_float2(h00, h01);
                    *(float2*)(hlast + (ch0 + 8) * Hn + gc) = make_float2(h10, h11);
                }
            }
        }
        // symmetric arrive (round-3-proven): ALL 256 threads arrive on the
        // peer's barrier; the storing threads' arrives carry release semantics
        // ordering their st.shared::cluster writes.
        if (t < Ln - 1)
            asm volatile("mbarrier.arrive.release.cluster.shared::cluster.b64 _, [%0];"
                         :: "r"(peer_mbar) : "memory");

        __syncthreads();   // local hbuf[np] + red reuse visibility
        pq ^= 1u;
    }
}

// ---------------------------------------------------------------------------
// Launch
// ---------------------------------------------------------------------------
extern "C" void kernel_launch(void* const* d_in, const int* in_sizes, int n_in,
                              void* d_out, int out_size)
{
    (void)in_sizes; (void)n_in;
    const float* x     = (const float*)d_in[0];
    const float* convw = (const float*)d_in[1];
    const float* convb = (const float*)d_in[2];
    const float* lng   = (const float*)d_in[3];
    const float* lnb   = (const float*)d_in[4];
    const float* Wih   = (const float*)d_in[5];
    const float* Whh   = (const float*)d_in[6];
    const float* rr    = (const float*)d_in[7];
    const float* ss    = (const float*)d_in[8];
    const float* bb    = (const float*)d_in[9];

    float* out = (float*)d_out;
    size_t h_elems = (size_t)Bn * En * Ln * Hn;
    float* hlast = nullptr;
    if ((size_t)out_size >= h_elems + (size_t)Bn * En * Hn)
        hlast = out + h_elems;

    float *p_ln, *p_u, *p_y, *p_pre;
    cudaGetSymbolAddress((void**)&p_ln, g_ln);
    cudaGetSymbolAddress((void**)&p_u, g_u);
    cudaGetSymbolAddress((void**)&p_y, g_y);
    cudaGetSymbolAddress((void**)&p_pre, g_pre);

    static int smem_set = 0;
    if (!smem_set) {
        cudaFuncSetAttribute(gemm3_kernel,
                             cudaFuncAttributeMaxDynamicSharedMemorySize, SM3_BYTES);
        cudaFuncSetAttribute(rec3_kernel,
                             cudaFuncAttributeMaxDynamicSharedMemorySize, R2_TOTAL);
        smem_set = 1;
    }

    ln_kernel<<<Bn * Ln, 256>>>(x, lng, lnb, p_ln);
    conv_kernel<<<(Bn * Ln * Dn) / 256, 256>>>(p_ln, convw, convb, p_u);

    for (int i = 0; i < NLn; i++) {
        const float* inx = (i == 0) ? p_u : p_y;
        gemm3_kernel<<<MROWS / 128, 256, SM3_BYTES>>>(
            inx,
            Wih + (size_t)i * Hn * Dn,
            rr + (size_t)i * En * Dn,
            ss + (size_t)i * En * Hn,
            bb + (size_t)i * Hn,
            p_pre, (i == 0) ? 1 : 0);

        float* yo = (i == NLn - 1) ? out : p_y;
        rec3_kernel<<<dim3(2, 16), 256, R2_TOTAL>>>(
            p_pre,
            Whh + (size_t)i * Hn * Hn,
            yo,
            (i == NLn - 1) ? hlast : (float*)nullptr);
    }
}

// round 12
// speedup vs baseline: 1.1170x; 1.1170x over previous
#include <cuda_runtime.h>
#include <cuda_bf16.h>
#include <cstdint>

// Problem constants
#define Bn 32
#define Ln 256
#define Dn 256
#define Hn 256
#define En 8
#define NLn 4
#define Kc 4
#define MROWS (Bn*En*Ln)     // 65536

#define SSTRIDE 264          // gemm smem stride

__device__ __forceinline__ float fast_tanh(float x)
{
    float y;
    asm("tanh.approx.f32 %0, %1;" : "=f"(y) : "f"(x));
    return y;
}

__device__ __forceinline__ uint32_t s2u(const void* p)
{
    uint32_t a;
    asm("{ .reg .u64 t; cvta.to.shared.u64 t, %1; cvt.u32.u64 %0, t; }"
        : "=r"(a) : "l"(p));
    return a;
}

// pack two fp32 -> bf16x2 (first arg in low half)
__device__ __forceinline__ unsigned int pbf2(float lo, float hi)
{
    unsigned int r;
    asm("cvt.rn.bf16x2.f32 %0, %1, %2;" : "=r"(r) : "f"(hi), "f"(lo));
    return r;
}

__device__ __forceinline__ float bhi(float x)
{
    return __bfloat162float(__float2bfloat16(x));
}

#define MMA_BF16(c, a, b) \
    asm volatile( \
        "mma.sync.aligned.m16n8k16.row.col.f32.bf16.bf16.f32 " \
        "{%0,%1,%2,%3}, {%4,%5,%6,%7}, {%8,%9}, {%0,%1,%2,%3};" \
        : "+f"((c)[0]), "+f"((c)[1]), "+f"((c)[2]), "+f"((c)[3]) \
        : "r"((a)[0]), "r"((a)[1]), "r"((a)[2]), "r"((a)[3]), \
          "r"((b)[0]), "r"((b)[1]))

__device__ __forceinline__ void mbar_wait_cluster(uint32_t mbar, uint32_t parity)
{
    asm volatile(
        "{\n\t"
        ".reg .pred P1;\n\t"
        "WL_%=:\n\t"
        "mbarrier.try_wait.parity.acquire.cluster.shared::cta.b64 P1, [%0], %1;\n\t"
        "@P1 bra.uni WD_%=;\n\t"
        "bra.uni WL_%=;\n\t"
        "WD_%=:\n\t"
        "}" :: "r"(mbar), "r"(parity) : "memory");
}

// Scratch (device globals - no allocation allowed)
__device__ float g_ln[Bn*Ln*Dn];                 // 8 MB
__device__ float g_u[Bn*Ln*Dn];                  // 8 MB
__device__ float g_y[(size_t)Bn*En*Ln*Hn];       // 64 MB
__device__ float g_pre[(size_t)Bn*En*Ln*Hn];     // 64 MB

// ---------------------------------------------------------------------------
// LayerNorm
// ---------------------------------------------------------------------------
__global__ void ln_kernel(const float* __restrict__ x, const float* __restrict__ g,
                          const float* __restrict__ bb, float* __restrict__ out)
{
    int token = blockIdx.x;
    int t = threadIdx.x;
    __shared__ float red[8];
    __shared__ float meanv, rstdv;

    float v = x[(size_t)token * Dn + t];

    float s = v;
    #pragma unroll
    for (int o = 16; o > 0; o >>= 1) s += __shfl_xor_sync(0xffffffffu, s, o);
    if ((t & 31) == 0) red[t >> 5] = s;
    __syncthreads();
    if (t == 0) {
        float m = 0.f;
        #pragma unroll
        for (int i = 0; i < 8; i++) m += red[i];
        meanv = m * (1.0f / Dn);
    }
    __syncthreads();

    float d = v - meanv;
    float sq = d * d;
    #pragma unroll
    for (int o = 16; o > 0; o >>= 1) sq += __shfl_xor_sync(0xffffffffu, sq, o);
    if ((t & 31) == 0) red[t >> 5] = sq;
    __syncthreads();
    if (t == 0) {
        float vv = 0.f;
        #pragma unroll
        for (int i = 0; i < 8; i++) vv += red[i];
        rstdv = rsqrtf(vv * (1.0f / Dn) + 1e-5f);
    }
    __syncthreads();

    out[(size_t)token * Dn + t] = d * rstdv * g[t] + bb[t];
}

// ---------------------------------------------------------------------------
// Depthwise causal conv1d (K=4, left pad 3) + bias
// ---------------------------------------------------------------------------
__global__ void conv_kernel(const float* __restrict__ ln, const float* __restrict__ cw,
                            const float* __restrict__ cb, float* __restrict__ u)
{
    int idx = blockIdx.x * 256 + threadIdx.x;
    int d  = idx & 255;
    int l  = (idx >> 8) & 255;
    int b0 = idx >> 16;
    float acc = cb[d];
    #pragma unroll
    for (int j = 0; j < Kc; j++) {
        int ls = l - (Kc - 1) + j;
        if (ls >= 0)
            acc += ln[((size_t)b0 * Ln + ls) * Dn + d] * cw[d * Kc + j];
    }
    u[idx] = acc;
}

// ---------------------------------------------------------------------------
// mma.sync bf16 split GEMM (round-5, proven): pre = (x*r) @ Wih^T * s + b
// ---------------------------------------------------------------------------
#define OFF_AHI 0
#define OFF_ALO (128*SSTRIDE)
#define OFF_BHI (256*SSTRIDE)
#define OFF_BLO (320*SSTRIDE)
#define SM3_ELEMS (384*SSTRIDE)
#define SM3_BYTES (SM3_ELEMS*2)

__global__ __launch_bounds__(256, 1)
void gemm3_kernel(const float* __restrict__ inx, const float* __restrict__ Wih,
                  const float* __restrict__ rv, const float* __restrict__ sv,
                  const float* __restrict__ bv, float* __restrict__ pre, int layer0)
{
    extern __shared__ __align__(16) __nv_bfloat16 sm[];
    int tid = threadIdx.x;
    int wid = tid >> 5;
    int lane = tid & 31;
    int bm = blockIdx.x;

    int eT = (bm >> 1) & 7;
    const float* rrow = rv + (size_t)eT * 256;

    {
        int row = tid >> 1;
        int kh  = (tid & 1) * 128;
        int rowA = bm * 128 + row;
        size_t srcRow = layer0 ? ((size_t)(rowA >> 11) * 256 + (rowA & 255))
                               : (size_t)rowA;
        const float* arow = inx + srcRow * 256 + kh;
        const float* rr   = rrow + kh;
        __nv_bfloat16* ahi = sm + OFF_AHI + row * SSTRIDE + kh;
        __nv_bfloat16* alo = sm + OFF_ALO + row * SSTRIDE + kh;
        #pragma unroll
        for (int g = 0; g < 32; g++) {
            float4 av = *(const float4*)(arow + g * 4);
            float4 rv4 = *(const float4*)(rr + g * 4);
            av.x *= rv4.x; av.y *= rv4.y; av.z *= rv4.z; av.w *= rv4.w;
            float vv[4] = {av.x, av.y, av.z, av.w};
            float hi[4], lo[4];
            #pragma unroll
            for (int qq = 0; qq < 4; qq++) {
                hi[qq] = bhi(vv[qq]);
                lo[qq] = vv[qq] - hi[qq];
            }
            *(uint2*)(ahi + g * 4) = make_uint2(pbf2(hi[0], hi[1]), pbf2(hi[2], hi[3]));
            *(uint2*)(alo + g * 4) = make_uint2(pbf2(lo[0], lo[1]), pbf2(lo[2], lo[3]));
        }
    }

    int warp_m = wid & 3;
    int warp_n = wid >> 2;
    int grp = lane >> 2;
    int tg  = lane & 3;

    for (int bn = 0; bn < 4; bn++) {
        __syncthreads();
        {
            int row = tid >> 2;
            int kq  = (tid & 3) * 64;
            const float* brow = Wih + (size_t)(bn * 64 + row) * 256 + kq;
            __nv_bfloat16* bhi_p = sm + OFF_BHI + row * SSTRIDE + kq;
            __nv_bfloat16* blo_p = sm + OFF_BLO + row * SSTRIDE + kq;
            #pragma unroll
            for (int g = 0; g < 16; g++) {
                float4 bvv = *(const float4*)(brow + g * 4);
                float vv[4] = {bvv.x, bvv.y, bvv.z, bvv.w};
                float hi[4], lo[4];
                #pragma unroll
                for (int qq = 0; qq < 4; qq++) {
                    hi[qq] = bhi(vv[qq]);
                    lo[qq] = vv[qq] - hi[qq];
                }
                *(uint2*)(bhi_p + g * 4) = make_uint2(pbf2(hi[0], hi[1]), pbf2(hi[2], hi[3]));
                *(uint2*)(blo_p + g * 4) = make_uint2(pbf2(lo[0], lo[1]), pbf2(lo[2], lo[3]));
            }
        }
        __syncthreads();

        float acc[2][4][4];
        #pragma unroll
        for (int mt = 0; mt < 2; mt++)
            #pragma unroll
            for (int n8 = 0; n8 < 4; n8++)
                #pragma unroll
                for (int qq = 0; qq < 4; qq++) acc[mt][n8][qq] = 0.f;

        #pragma unroll 4
        for (int k0 = 0; k0 < 256; k0 += 16) {
            uint32_t ahi_f[2][4], alo_f[2][4];
            #pragma unroll
            for (int mt = 0; mt < 2; mt++) {
                int r0 = warp_m * 32 + mt * 16 + grp;
                const __nv_bfloat16* pHi = sm + OFF_AHI + r0 * SSTRIDE + k0 + tg * 2;
                const __nv_bfloat16* pLo = sm + OFF_ALO + r0 * SSTRIDE + k0 + tg * 2;
                ahi_f[mt][0] = *(const uint32_t*)(pHi);
                ahi_f[mt][1] = *(const uint32_t*)(pHi + 8 * SSTRIDE);
                ahi_f[mt][2] = *(const uint32_t*)(pHi + 8);
                ahi_f[mt][3] = *(const uint32_t*)(pHi + 8 * SSTRIDE + 8);
                alo_f[mt][0] = *(const uint32_t*)(pLo);
                alo_f[mt][1] = *(const uint32_t*)(pLo + 8 * SSTRIDE);
                alo_f[mt][2] = *(const uint32_t*)(pLo + 8);
                alo_f[mt][3] = *(const uint32_t*)(pLo + 8 * SSTRIDE + 8);
            }
            uint32_t bhi_f[4][2], blo_f[4][2];
            #pragma unroll
            for (int n8 = 0; n8 < 4; n8++) {
                int c0 = warp_n * 32 + n8 * 8 + grp;
                const __nv_bfloat16* pHi = sm + OFF_BHI + c0 * SSTRIDE + k0 + tg * 2;
                const __nv_bfloat16* pLo = sm + OFF_BLO + c0 * SSTRIDE + k0 + tg * 2;
                bhi_f[n8][0] = *(const uint32_t*)(pHi);
                bhi_f[n8][1] = *(const uint32_t*)(pHi + 8);
                blo_f[n8][0] = *(const uint32_t*)(pLo);
                blo_f[n8][1] = *(const uint32_t*)(pLo + 8);
            }
            #pragma unroll
            for (int mt = 0; mt < 2; mt++)
                #pragma unroll
                for (int n8 = 0; n8 < 4; n8++) {
                    MMA_BF16(acc[mt][n8], ahi_f[mt], bhi_f[n8]);
                    MMA_BF16(acc[mt][n8], ahi_f[mt], blo_f[n8]);
                    MMA_BF16(acc[mt][n8], alo_f[mt], bhi_f[n8]);
                }
        }

        const float* srow = sv + (size_t)eT * 256;
        #pragma unroll
        for (int mt = 0; mt < 2; mt++) {
            int rloc = warp_m * 32 + mt * 16 + grp;
            size_t row0 = (size_t)bm * 128 + rloc;
            #pragma unroll
            for (int n8 = 0; n8 < 4; n8++) {
                int col = bn * 64 + warp_n * 32 + n8 * 8 + tg * 2;
                float s0 = srow[col], s1 = srow[col + 1];
                float b0 = bv[col], b1 = bv[col + 1];
                float2 o0, o1;
                o0.x = acc[mt][n8][0] * s0 + b0;
                o0.y = acc[mt][n8][1] * s1 + b1;
                o1.x = acc[mt][n8][2] * s0 + b0;
                o1.y = acc[mt][n8][3] * s1 + b1;
                *(float2*)(pre + row0 * 256 + col) = o0;
                *(float2*)(pre + (row0 + 8) * 256 + col) = o1;
            }
        }
    }
}

// ---------------------------------------------------------------------------
// Recurrence (scalar fp32, cluster 2): round-3 skeleton + 3 micro-opts:
//  - merged 512-count mbarrier (own release.cta + peer release.cluster
//    arrives) replaces end-of-step __syncthreads
//  - 4 K-slices of 64 (thread = 2 outs x 4 chains x 64 j) -> reduce = 8 LDS
//  - pre prefetched one full step ahead
// ---------------------------------------------------------------------------
__global__ __launch_bounds__(256, 1) __cluster_dims__(2, 1, 1)
void rec_kernel(const float* __restrict__ pre, const float* __restrict__ Whh,
                float* __restrict__ yout, float* __restrict__ hlast)
{
    int q = blockIdx.x;        // cluster rank 0/1
    int c = blockIdx.y;        // cluster id 0..63
    int tid = threadIdx.x;
    int tz = tid >> 6;         // K-slice 0..3, j in [tz*64, tz*64+64)
    int to = tid & 63;         // output pair: local outs to*2, to*2+1

    // W in registers: w[o 0..1][j 0..63] for rows q*128 + to*2 + o
    float w[2][64];
    #pragma unroll
    for (int o = 0; o < 2; o++) {
        const float* wr = Whh + (size_t)(q * 128 + to * 2 + o) * Hn + tz * 64;
        #pragma unroll
        for (int j4 = 0; j4 < 16; j4++) {
            float4 v = *(const float4*)(wr + j4 * 4);
            w[o][j4 * 4 + 0] = v.x;
            w[o][j4 * 4 + 1] = v.y;
            w[o][j4 * 4 + 2] = v.z;
            w[o][j4 * 4 + 3] = v.w;
        }
    }

    __shared__ __align__(16) float hbuf[2][4][256];
    __shared__ __align__(16) float part[4][4][128];
    __shared__ __align__(8) unsigned long long mbar_s;

    for (int i = tid; i < 4 * 256; i += 256) ((float*)hbuf[0])[i] = 0.f;
    uint32_t my_mbar = s2u(&mbar_s);
    if (tid == 0) {
        asm volatile("mbarrier.init.shared.b64 [%0], 512;" :: "r"(my_mbar) : "memory");
    }
    __syncthreads();
    asm volatile("barrier.cluster.arrive.aligned;\n\t"
                 "barrier.cluster.wait.aligned;" ::: "memory");

    // reduce mapping: thread handles out rk for chains m0, m1
    int rk = tid & 127;
    int mh = tid >> 7;
    int m0 = mh * 2, m1 = m0 + 1;
    int kg = q * 128 + rk;
    size_t be0 = (size_t)c * 4;

    uint32_t peer_mbar;
    asm("mapa.shared::cluster.u32 %0, %1, %2;" : "=r"(peer_mbar)
        : "r"(my_mbar), "r"(q ^ 1));

    uint32_t pa0[2], pa1[2];
    #pragma unroll
    for (int p = 0; p < 2; p++) {
        uint32_t a0 = s2u(&hbuf[p][m0][kg]);
        uint32_t a1 = s2u(&hbuf[p][m1][kg]);
        asm("mapa.shared::cluster.u32 %0, %1, %2;" : "=r"(pa0[p]) : "r"(a0), "r"(q ^ 1));
        asm("mapa.shared::cluster.u32 %0, %1, %2;" : "=r"(pa1[p]) : "r"(a1), "r"(q ^ 1));
    }

    const float* pre0 = pre + ((be0 + m0) * Ln) * Hn + kg;
    const float* pre1 = pre + ((be0 + m1) * Ln) * Hn + kg;
    float* y0 = yout + ((be0 + m0) * Ln) * Hn + kg;
    float* y1 = yout + ((be0 + m1) * Ln) * Hn + kg;

    // prefetch pre for t=0
    float pv0 = pre0[0];
    float pv1 = pre1[0];

    int pq = 0;
    unsigned int ph = 0;
    for (int t = 0; t < Ln; t++) {
        if (t > 0) {
            mbar_wait_cluster(my_mbar, ph);
            ph ^= 1u;
        }

        // prefetch pre for t+1 (covered by the whole step's compute)
        float pn0 = 0.f, pn1 = 0.f;
        if (t < Ln - 1) {
            pn0 = pre0[(t + 1) * Hn];
            pn1 = pre1[(t + 1) * Hn];
        }

        // partial matvec: 2 outs x 4 chains over this slice's 64 j
        float acc[4][2];
        #pragma unroll
        for (int m = 0; m < 4; m++) {
            acc[m][0] = 0.f;
            acc[m][1] = 0.f;
        }

        #pragma unroll
        for (int j4 = 0; j4 < 16; j4++) {
            float4 h0 = *(const float4*)&hbuf[pq][0][tz * 64 + j4 * 4];
            float4 h1 = *(const float4*)&hbuf[pq][1][tz * 64 + j4 * 4];
            float4 h2 = *(const float4*)&hbuf[pq][2][tz * 64 + j4 * 4];
            float4 h3 = *(const float4*)&hbuf[pq][3][tz * 64 + j4 * 4];
            float hv0[4] = {h0.x, h0.y, h0.z, h0.w};
            float hv1[4] = {h1.x, h1.y, h1.z, h1.w};
            float hv2[4] = {h2.x, h2.y, h2.z, h2.w};
            float hv3[4] = {h3.x, h3.y, h3.z, h3.w};
            #pragma unroll
            for (int jj = 0; jj < 4; jj++) {
                int j = j4 * 4 + jj;
                #pragma unroll
                for (int o = 0; o < 2; o++) {
                    acc[0][o] += w[o][j] * hv0[jj];
                    acc[1][o] += w[o][j] * hv1[jj];
                    acc[2][o] += w[o][j] * hv2[jj];
                    acc[3][o] += w[o][j] * hv3[jj];
                }
            }
        }
        #pragma unroll
        for (int m = 0; m < 4; m++)
            *(float2*)&part[tz][m][to * 2] = make_float2(acc[m][0], acc[m][1]);
        __syncthreads();

        // reduce 4 slices, add pre, tanh
        float s0 = pv0, s1 = pv1;
        #pragma unroll
        for (int z = 0; z < 4; z++) {
            s0 += part[z][m0][rk];
            s1 += part[z][m1][rk];
        }
        float h0n = fast_tanh(s0);
        float h1n = fast_tanh(s1);

        y0[t * Hn] = h0n;
        y1[t * Hn] = h1n;

        int np = pq ^ 1;
        hbuf[np][m0][kg] = h0n;
        hbuf[np][m1][kg] = h1n;

        if (t < Ln - 1) {
            // remote h write, then release-arrives:
            //   peer mbar (release.cluster orders the DSMEM stores)
            //   own mbar (release.cta orders the local hbuf/part accesses)
            asm volatile("st.shared::cluster.f32 [%0], %1;" :: "r"(pa0[np]), "f"(h0n));
            asm volatile("st.shared::cluster.f32 [%0], %1;" :: "r"(pa1[np]), "f"(h1n));
            asm volatile("mbarrier.arrive.release.cluster.shared::cluster.b64 _, [%0];"
                         :: "r"(peer_mbar) : "memory");
            asm volatile("mbarrier.arrive.release.cta.shared::cta.b64 _, [%0];"
                         :: "r"(my_mbar) : "memory");
        }

        if (hlast != nullptr && t == Ln - 1) {
            hlast[(be0 + m0) * Hn + kg] = h0n;
            hlast[(be0 + m1) * Hn + kg] = h1n;
        }

        pv0 = pn0;
        pv1 = pn1;
        pq = np;
    }
}

// ---------------------------------------------------------------------------
// Launch
// ---------------------------------------------------------------------------
extern "C" void kernel_launch(void* const* d_in, const int* in_sizes, int n_in,
                              void* d_out, int out_size)
{
    (void)in_sizes; (void)n_in;
    const float* x     = (const float*)d_in[0];
    const float* convw = (const float*)d_in[1];
    const float* convb = (const float*)d_in[2];
    const float* lng   = (const float*)d_in[3];
    const float* lnb   = (const float*)d_in[4];
    const float* Wih   = (const float*)d_in[5];
    const float* Whh   = (const float*)d_in[6];
    const float* rr    = (const float*)d_in[7];
    const float* ss    = (const float*)d_in[8];
    const float* bb    = (const float*)d_in[9];

    float* out = (float*)d_out;
    size_t h_elems = (size_t)Bn * En * Ln * Hn;
    float* hlast = nullptr;
    if ((size_t)out_size >= h_elems + (size_t)Bn * En * Hn)
        hlast = out + h_elems;

    float *p_ln, *p_u, *p_y, *p_pre;
    cudaGetSymbolAddress((void**)&p_ln, g_ln);
    cudaGetSymbolAddress((void**)&p_u, g_u);
    cudaGetSymbolAddress((void**)&p_y, g_y);
    cudaGetSymbolAddress((void**)&p_pre, g_pre);

    static int smem_set = 0;
    if (!smem_set) {
        cudaFuncSetAttribute(gemm3_kernel,
                             cudaFuncAttributeMaxDynamicSharedMemorySize, SM3_BYTES);
        smem_set = 1;
    }

    ln_kernel<<<Bn * Ln, 256>>>(x, lng, lnb, p_ln);
    conv_kernel<<<(Bn * Ln * Dn) / 256, 256>>>(p_ln, convw, convb, p_u);

    for (int i = 0; i < NLn; i++) {
        const float* inx = (i == 0) ? p_u : p_y;
        gemm3_kernel<<<MROWS / 128, 256, SM3_BYTES>>>(
            inx,
            Wih + (size_t)i * Hn * Dn,
            rr + (size_t)i * En * Dn,
            ss + (size_t)i * En * Hn,
            bb + (size_t)i * Hn,
            p_pre, (i == 0) ? 1 : 0);

        float* yo = (i == NLn - 1) ? out : p_y;
        rec_kernel<<<dim3(2, 64), 256>>>(
            p_pre,
            Whh + (size_t)i * Hn * Hn,
            yo,
            (i == NLn - 1) ? hlast : (float*)nullptr);
    }
}

// round 13
// speedup vs baseline: 1.1402x; 1.0207x over previous
#include <cuda_runtime.h>
#include <cuda_bf16.h>
#include <cstdint>

// Problem constants
#define Bn 32
#define Ln 256
#define Dn 256
#define Hn 256
#define En 8
#define NLn 4
#define Kc 4
#define MROWS (Bn*En*Ln)     // 65536

#define SSTRIDE 264          // gemm smem stride

__device__ __forceinline__ float fast_tanh(float x)
{
    float y;
    asm("tanh.approx.f32 %0, %1;" : "=f"(y) : "f"(x));
    return y;
}

__device__ __forceinline__ uint32_t s2u(const void* p)
{
    uint32_t a;
    asm("{ .reg .u64 t; cvta.to.shared.u64 t, %1; cvt.u32.u64 %0, t; }"
        : "=r"(a) : "l"(p));
    return a;
}

// pack two fp32 -> bf16x2 (first arg in low half)
__device__ __forceinline__ unsigned int pbf2(float lo, float hi)
{
    unsigned int r;
    asm("cvt.rn.bf16x2.f32 %0, %1, %2;" : "=r"(r) : "f"(hi), "f"(lo));
    return r;
}

__device__ __forceinline__ float bhi(float x)
{
    return __bfloat162float(__float2bfloat16(x));
}

#define MMA_BF16(c, a, b) \
    asm volatile( \
        "mma.sync.aligned.m16n8k16.row.col.f32.bf16.bf16.f32 " \
        "{%0,%1,%2,%3}, {%4,%5,%6,%7}, {%8,%9}, {%0,%1,%2,%3};" \
        : "+f"((c)[0]), "+f"((c)[1]), "+f"((c)[2]), "+f"((c)[3]) \
        : "r"((a)[0]), "r"((a)[1]), "r"((a)[2]), "r"((a)[3]), \
          "r"((b)[0]), "r"((b)[1]))

__device__ __forceinline__ void mbar_wait_cluster(uint32_t mbar, uint32_t parity)
{
    asm volatile(
        "{\n\t"
        ".reg .pred P1;\n\t"
        "WL_%=:\n\t"
        "mbarrier.try_wait.parity.acquire.cluster.shared::cta.b64 P1, [%0], %1;\n\t"
        "@P1 bra.uni WD_%=;\n\t"
        "bra.uni WL_%=;\n\t"
        "WD_%=:\n\t"
        "}" :: "r"(mbar), "r"(parity) : "memory");
}

// Scratch (device globals - no allocation allowed)
__device__ float g_ln[Bn*Ln*Dn];                 // 8 MB
__device__ float g_u[Bn*Ln*Dn];                  // 8 MB
__device__ float g_y[(size_t)Bn*En*Ln*Hn];       // 64 MB
__device__ float g_pre[(size_t)Bn*En*Ln*Hn];     // 64 MB

// ---------------------------------------------------------------------------
// LayerNorm
// ---------------------------------------------------------------------------
__global__ void ln_kernel(const float* __restrict__ x, const float* __restrict__ g,
                          const float* __restrict__ bb, float* __restrict__ out)
{
    int token = blockIdx.x;
    int t = threadIdx.x;
    __shared__ float red[8];
    __shared__ float meanv, rstdv;

    float v = x[(size_t)token * Dn + t];

    float s = v;
    #pragma unroll
    for (int o = 16; o > 0; o >>= 1) s += __shfl_xor_sync(0xffffffffu, s, o);
    if ((t & 31) == 0) red[t >> 5] = s;
    __syncthreads();
    if (t == 0) {
        float m = 0.f;
        #pragma unroll
        for (int i = 0; i < 8; i++) m += red[i];
        meanv = m * (1.0f / Dn);
    }
    __syncthreads();

    float d = v - meanv;
    float sq = d * d;
    #pragma unroll
    for (int o = 16; o > 0; o >>= 1) sq += __shfl_xor_sync(0xffffffffu, sq, o);
    if ((t & 31) == 0) red[t >> 5] = sq;
    __syncthreads();
    if (t == 0) {
        float vv = 0.f;
        #pragma unroll
        for (int i = 0; i < 8; i++) vv += red[i];
        rstdv = rsqrtf(vv * (1.0f / Dn) + 1e-5f);
    }
    __syncthreads();

    out[(size_t)token * Dn + t] = d * rstdv * g[t] + bb[t];
}

// ---------------------------------------------------------------------------
// Depthwise causal conv1d (K=4, left pad 3) + bias
// ---------------------------------------------------------------------------
__global__ void conv_kernel(const float* __restrict__ ln, const float* __restrict__ cw,
                            const float* __restrict__ cb, float* __restrict__ u)
{
    int idx = blockIdx.x * 256 + threadIdx.x;
    int d  = idx & 255;
    int l  = (idx >> 8) & 255;
    int b0 = idx >> 16;
    float acc = cb[d];
    #pragma unroll
    for (int j = 0; j < Kc; j++) {
        int ls = l - (Kc - 1) + j;
        if (ls >= 0)
            acc += ln[((size_t)b0 * Ln + ls) * Dn + d] * cw[d * Kc + j];
    }
    u[idx] = acc;
}

// ---------------------------------------------------------------------------
// mma.sync bf16 split GEMM (round-5, proven): pre = (x*r) @ Wih^T * s + b
// ---------------------------------------------------------------------------
#define OFF_AHI 0
#define OFF_ALO (128*SSTRIDE)
#define OFF_BHI (256*SSTRIDE)
#define OFF_BLO (320*SSTRIDE)
#define SM3_ELEMS (384*SSTRIDE)
#define SM3_BYTES (SM3_ELEMS*2)

__global__ __launch_bounds__(256, 1)
void gemm3_kernel(const float* __restrict__ inx, const float* __restrict__ Wih,
                  const float* __restrict__ rv, const float* __restrict__ sv,
                  const float* __restrict__ bv, float* __restrict__ pre, int layer0)
{
    extern __shared__ __align__(16) __nv_bfloat16 sm[];
    int tid = threadIdx.x;
    int wid = tid >> 5;
    int lane = tid & 31;
    int bm = blockIdx.x;

    int eT = (bm >> 1) & 7;
    const float* rrow = rv + (size_t)eT * 256;

    {
        int row = tid >> 1;
        int kh  = (tid & 1) * 128;
        int rowA = bm * 128 + row;
        size_t srcRow = layer0 ? ((size_t)(rowA >> 11) * 256 + (rowA & 255))
                               : (size_t)rowA;
        const float* arow = inx + srcRow * 256 + kh;
        const float* rr   = rrow + kh;
        __nv_bfloat16* ahi = sm + OFF_AHI + row * SSTRIDE + kh;
        __nv_bfloat16* alo = sm + OFF_ALO + row * SSTRIDE + kh;
        #pragma unroll
        for (int g = 0; g < 32; g++) {
            float4 av = *(const float4*)(arow + g * 4);
            float4 rv4 = *(const float4*)(rr + g * 4);
            av.x *= rv4.x; av.y *= rv4.y; av.z *= rv4.z; av.w *= rv4.w;
            float vv[4] = {av.x, av.y, av.z, av.w};
            float hi[4], lo[4];
            #pragma unroll
            for (int qq = 0; qq < 4; qq++) {
                hi[qq] = bhi(vv[qq]);
                lo[qq] = vv[qq] - hi[qq];
            }
            *(uint2*)(ahi + g * 4) = make_uint2(pbf2(hi[0], hi[1]), pbf2(hi[2], hi[3]));
            *(uint2*)(alo + g * 4) = make_uint2(pbf2(lo[0], lo[1]), pbf2(lo[2], lo[3]));
        }
    }

    int warp_m = wid & 3;
    int warp_n = wid >> 2;
    int grp = lane >> 2;
    int tg  = lane & 3;

    for (int bn = 0; bn < 4; bn++) {
        __syncthreads();
        {
            int row = tid >> 2;
            int kq  = (tid & 3) * 64;
            const float* brow = Wih + (size_t)(bn * 64 + row) * 256 + kq;
            __nv_bfloat16* bhi_p = sm + OFF_BHI + row * SSTRIDE + kq;
            __nv_bfloat16* blo_p = sm + OFF_BLO + row * SSTRIDE + kq;
            #pragma unroll
            for (int g = 0; g < 16; g++) {
                float4 bvv = *(const float4*)(brow + g * 4);
                float vv[4] = {bvv.x, bvv.y, bvv.z, bvv.w};
                float hi[4], lo[4];
                #pragma unroll
                for (int qq = 0; qq < 4; qq++) {
                    hi[qq] = bhi(vv[qq]);
                    lo[qq] = vv[qq] - hi[qq];
                }
                *(uint2*)(bhi_p + g * 4) = make_uint2(pbf2(hi[0], hi[1]), pbf2(hi[2], hi[3]));
                *(uint2*)(blo_p + g * 4) = make_uint2(pbf2(lo[0], lo[1]), pbf2(lo[2], lo[3]));
            }
        }
        __syncthreads();

        float acc[2][4][4];
        #pragma unroll
        for (int mt = 0; mt < 2; mt++)
            #pragma unroll
            for (int n8 = 0; n8 < 4; n8++)
                #pragma unroll
                for (int qq = 0; qq < 4; qq++) acc[mt][n8][qq] = 0.f;

        #pragma unroll 4
        for (int k0 = 0; k0 < 256; k0 += 16) {
            uint32_t ahi_f[2][4], alo_f[2][4];
            #pragma unroll
            for (int mt = 0; mt < 2; mt++) {
                int r0 = warp_m * 32 + mt * 16 + grp;
                const __nv_bfloat16* pHi = sm + OFF_AHI + r0 * SSTRIDE + k0 + tg * 2;
                const __nv_bfloat16* pLo = sm + OFF_ALO + r0 * SSTRIDE + k0 + tg * 2;
                ahi_f[mt][0] = *(const uint32_t*)(pHi);
                ahi_f[mt][1] = *(const uint32_t*)(pHi + 8 * SSTRIDE);
                ahi_f[mt][2] = *(const uint32_t*)(pHi + 8);
                ahi_f[mt][3] = *(const uint32_t*)(pHi + 8 * SSTRIDE + 8);
                alo_f[mt][0] = *(const uint32_t*)(pLo);
                alo_f[mt][1] = *(const uint32_t*)(pLo + 8 * SSTRIDE);
                alo_f[mt][2] = *(const uint32_t*)(pLo + 8);
                alo_f[mt][3] = *(const uint32_t*)(pLo + 8 * SSTRIDE + 8);
            }
            uint32_t bhi_f[4][2], blo_f[4][2];
            #pragma unroll
            for (int n8 = 0; n8 < 4; n8++) {
                int c0 = warp_n * 32 + n8 * 8 + grp;
                const __nv_bfloat16* pHi = sm + OFF_BHI + c0 * SSTRIDE + k0 + tg * 2;
                const __nv_bfloat16* pLo = sm + OFF_BLO + c0 * SSTRIDE + k0 + tg * 2;
                bhi_f[n8][0] = *(const uint32_t*)(pHi);
                bhi_f[n8][1] = *(const uint32_t*)(pHi + 8);
                blo_f[n8][0] = *(const uint32_t*)(pLo);
                blo_f[n8][1] = *(const uint32_t*)(pLo + 8);
            }
            #pragma unroll
            for (int mt = 0; mt < 2; mt++)
                #pragma unroll
                for (int n8 = 0; n8 < 4; n8++) {
                    MMA_BF16(acc[mt][n8], ahi_f[mt], bhi_f[n8]);
                    MMA_BF16(acc[mt][n8], ahi_f[mt], blo_f[n8]);
                    MMA_BF16(acc[mt][n8], alo_f[mt], bhi_f[n8]);
                }
        }

        const float* srow = sv + (size_t)eT * 256;
        #pragma unroll
        for (int mt = 0; mt < 2; mt++) {
            int rloc = warp_m * 32 + mt * 16 + grp;
            size_t row0 = (size_t)bm * 128 + rloc;
            #pragma unroll
            for (int n8 = 0; n8 < 4; n8++) {
                int col = bn * 64 + warp_n * 32 + n8 * 8 + tg * 2;
                float s0 = srow[col], s1 = srow[col + 1];
                float b0 = bv[col], b1 = bv[col + 1];
                float2 o0, o1;
                o0.x = acc[mt][n8][0] * s0 + b0;
                o0.y = acc[mt][n8][1] * s1 + b1;
                o1.x = acc[mt][n8][2] * s0 + b0;
                o1.y = acc[mt][n8][3] * s1 + b1;
                *(float2*)(pre + row0 * 256 + col) = o0;
                *(float2*)(pre + (row0 + 8) * 256 + col) = o1;
            }
        }
    }
}

// ---------------------------------------------------------------------------
// Recurrence: round-3 skeleton EXACTLY (8 K-slices, 256-count mbar, end
// __syncthreads), plus two micro-edits:
//  (1) DSMEM stores + peer release-arrive issued BEFORE the global y stores
//  (2) pre prefetched one full step ahead (covered by the FFMA block)
// ---------------------------------------------------------------------------
__global__ __launch_bounds__(256, 1) __cluster_dims__(2, 1, 1)
void rec_kernel(const float* __restrict__ pre, const float* __restrict__ Whh,
                float* __restrict__ yout, float* __restrict__ hlast)
{
    int q = blockIdx.x;        // cluster rank 0/1
    int c = blockIdx.y;        // cluster id 0..63
    int tid = threadIdx.x;
    int tz = tid >> 5;         // warp -> j slice [tz*32, tz*32+32)
    int tx = tid & 31;         // k tile -> rows tx*4 .. tx*4+3 (local)

    // W half in registers
    float w[4][32];
    #pragma unroll
    for (int a = 0; a < 4; a++) {
        const float* wr = Whh + (size_t)(q * 128 + tx * 4 + a) * Hn + tz * 32;
        #pragma unroll
        for (int j4 = 0; j4 < 8; j4++) {
            float4 v = *(const float4*)(wr + j4 * 4);
            w[a][j4 * 4 + 0] = v.x;
            w[a][j4 * 4 + 1] = v.y;
            w[a][j4 * 4 + 2] = v.z;
            w[a][j4 * 4 + 3] = v.w;
        }
    }

    __shared__ __align__(16) float hbuf[2][4][256];
    __shared__ __align__(16) float part[32][128];
    __shared__ __align__(8) unsigned long long mbar_s;

    for (int i = tid; i < 4 * 256; i += 256) ((float*)hbuf[0])[i] = 0.f;
    if (tid == 0) {
        uint32_t mb = s2u(&mbar_s);
        asm volatile("mbarrier.init.shared.b64 [%0], 256;" :: "r"(mb) : "memory");
    }
    __syncthreads();
    asm volatile("barrier.cluster.arrive.aligned;\n\t"
                 "barrier.cluster.wait.aligned;" ::: "memory");

    int rk = tid & 127;
    int mh = tid >> 7;
    int m0 = mh * 2, m1 = m0 + 1;
    int kg = q * 128 + rk;
    size_t be0 = (size_t)c * 4;

    uint32_t my_mbar = s2u(&mbar_s);
    uint32_t peer_mbar;
    asm("mapa.shared::cluster.u32 %0, %1, %2;" : "=r"(peer_mbar)
        : "r"(my_mbar), "r"(q ^ 1));

    uint32_t pa0[2], pa1[2];
    #pragma unroll
    for (int p = 0; p < 2; p++) {
        uint32_t a0 = s2u(&hbuf[p][m0][kg]);
        uint32_t a1 = s2u(&hbuf[p][m1][kg]);
        asm("mapa.shared::cluster.u32 %0, %1, %2;" : "=r"(pa0[p]) : "r"(a0), "r"(q ^ 1));
        asm("mapa.shared::cluster.u32 %0, %1, %2;" : "=r"(pa1[p]) : "r"(a1), "r"(q ^ 1));
    }

    const float* pre0 = pre + ((be0 + m0) * Ln) * Hn + kg;
    const float* pre1 = pre + ((be0 + m1) * Ln) * Hn + kg;
    float* y0 = yout + ((be0 + m0) * Ln) * Hn + kg;
    float* y1 = yout + ((be0 + m1) * Ln) * Hn + kg;

    // prefetch pre for t=0
    float pv0 = pre0[0];
    float pv1 = pre1[0];

    int pq = 0;
    unsigned int ph = 0;
    for (int t = 0; t < Ln; t++) {
        if (t > 0) {
            mbar_wait_cluster(my_mbar, ph);
            ph ^= 1u;
        }

        // prefetch pre for t+1 (latency covered by the FFMA block below)
        float pn0 = 0.f, pn1 = 0.f;
        if (t < Ln - 1) {
            pn0 = pre0[(t + 1) * Hn];
            pn1 = pre1[(t + 1) * Hn];
        }

        // partial matvec over this warp's j slice
        float acc[4][4];
        #pragma unroll
        for (int m = 0; m < 4; m++)
            #pragma unroll
            for (int a = 0; a < 4; a++) acc[m][a] = 0.f;

        #pragma unroll
        for (int j4 = 0; j4 < 8; j4++) {
            float4 h0 = *(const float4*)&hbuf[pq][0][tz * 32 + j4 * 4];
            float4 h1 = *(const float4*)&hbuf[pq][1][tz * 32 + j4 * 4];
            float4 h2 = *(const float4*)&hbuf[pq][2][tz * 32 + j4 * 4];
            float4 h3 = *(const float4*)&hbuf[pq][3][tz * 32 + j4 * 4];
            float hv0[4] = {h0.x, h0.y, h0.z, h0.w};
            float hv1[4] = {h1.x, h1.y, h1.z, h1.w};
            float hv2[4] = {h2.x, h2.y, h2.z, h2.w};
            float hv3[4] = {h3.x, h3.y, h3.z, h3.w};
            #pragma unroll
            for (int jj = 0; jj < 4; jj++) {
                int j = j4 * 4 + jj;
                #pragma unroll
                for (int a = 0; a < 4; a++) {
                    acc[0][a] += w[a][j] * hv0[jj];
                    acc[1][a] += w[a][j] * hv1[jj];
                    acc[2][a] += w[a][j] * hv2[jj];
                    acc[3][a] += w[a][j] * hv3[jj];
                }
            }
        }
        #pragma unroll
        for (int m = 0; m < 4; m++)
            *(float4*)&part[tz * 4 + m][tx * 4] =
                make_float4(acc[m][0], acc[m][1], acc[m][2], acc[m][3]);
        __syncthreads();

        // reduce 8 K-slices, add pre, tanh
        float s0 = pv0, s1 = pv1;
        #pragma unroll
        for (int z = 0; z < 8; z++) {
            s0 += part[z * 4 + m0][rk];
            s1 += part[z * 4 + m1][rk];
        }
        float h0n = fast_tanh(s0);
        float h1n = fast_tanh(s1);

        int np = pq ^ 1;
        hbuf[np][m0][kg] = h0n;
        hbuf[np][m1][kg] = h1n;

        // (1) wake the peer FIRST: DSMEM stores + release-arrive before the
        //     (slow-issue) global y stores
        if (t < Ln - 1) {
            asm volatile("st.shared::cluster.f32 [%0], %1;" :: "r"(pa0[np]), "f"(h0n));
            asm volatile("st.shared::cluster.f32 [%0], %1;" :: "r"(pa1[np]), "f"(h1n));
            asm volatile("mbarrier.arrive.release.cluster.shared::cluster.b64 _, [%0];"
                         :: "r"(peer_mbar) : "memory");
        }

        y0[t * Hn] = h0n;
        y1[t * Hn] = h1n;

        if (hlast != nullptr && t == Ln - 1) {
            hlast[(be0 + m0) * Hn + kg] = h0n;
            hlast[(be0 + m1) * Hn + kg] = h1n;
        }

        pv0 = pn0;
        pv1 = pn1;
        __syncthreads();   // part reuse + local hbuf[np] visibility
        pq = np;
    }
}

// ---------------------------------------------------------------------------
// Launch
// ---------------------------------------------------------------------------
extern "C" void kernel_launch(void* const* d_in, const int* in_sizes, int n_in,
                              void* d_out, int out_size)
{
    (void)in_sizes; (void)n_in;
    const float* x     = (const float*)d_in[0];
    const float* convw = (const float*)d_in[1];
    const float* convb = (const float*)d_in[2];
    const float* lng   = (const float*)d_in[3];
    const float* lnb   = (const float*)d_in[4];
    const float* Wih   = (const float*)d_in[5];
    const float* Whh   = (const float*)d_in[6];
    const float* rr    = (const float*)d_in[7];
    const float* ss    = (const float*)d_in[8];
    const float* bb    = (const float*)d_in[9];

    float* out = (float*)d_out;
    size_t h_elems = (size_t)Bn * En * Ln * Hn;
    float* hlast = nullptr;
    if ((size_t)out_size >= h_elems + (size_t)Bn * En * Hn)
        hlast = out + h_elems;

    float *p_ln, *p_u, *p_y, *p_pre;
    cudaGetSymbolAddress((void**)&p_ln, g_ln);
    cudaGetSymbolAddress((void**)&p_u, g_u);
    cudaGetSymbolAddress((void**)&p_y, g_y);
    cudaGetSymbolAddress((void**)&p_pre, g_pre);

    static int smem_set = 0;
    if (!smem_set) {
        cudaFuncSetAttribute(gemm3_kernel,
                             cudaFuncAttributeMaxDynamicSharedMemorySize, SM3_BYTES);
        smem_set = 1;
    }

    ln_kernel<<<Bn * Ln, 256>>>(x, lng, lnb, p_ln);
    conv_kernel<<<(Bn * Ln * Dn) / 256, 256>>>(p_ln, convw, convb, p_u);

    for (int i = 0; i < NLn; i++) {
        const float* inx = (i == 0) ? p_u : p_y;
        gemm3_kernel<<<MROWS / 128, 256, SM3_BYTES>>>(
            inx,
            Wih + (size_t)i * Hn * Dn,
            rr + (size_t)i * En * Dn,
            ss + (size_t)i * En * Hn,
            bb + (size_t)i * Hn,
            p_pre, (i == 0) ? 1 : 0);

        float* yo = (i == NLn - 1) ? out : p_y;
        rec_kernel<<<dim3(2, 64), 256>>>(
            p_pre,
            Whh + (size_t)i * Hn * Hn,
            yo,
            (i == NLn - 1) ? hlast : (float*)nullptr);
    }
}